// round 12
// baseline (speedup 1.0000x reference)
#include <cuda_runtime.h>
#include <cuda_fp16.h>
#include <cstdint>
#include <math.h>

// Bahdanau additive attention, sm_103 base target (no tcgen05).
// R12: k2 N-slab widened to 256 (A-traffic halves: 1GB -> 512MB; barriers
// per MMA halve). 512 threads, 16 warps 4m x 4n, 3-stage cp.async.

#define BATCH 32
#define TSEQ  2048
#define HDIM  1024
#define UDIM  1024
#define BT    (BATCH * TSEQ)

// ---------------------------------------------------------------- scratch
__device__ float g_score[BT];
__device__ float g_decproj[BATCH * UDIM];
__device__ __half g_enc_h[(size_t)BT * HDIM];     // 128 MB
__device__ __half g_ua_t[(size_t)UDIM * HDIM];    // transposed [U][H]

// ---------------------------------------------------------------- helpers
__device__ __forceinline__ uint32_t smem_u32(const void* p) {
    uint32_t a;
    asm("{ .reg .u64 t; cvta.to.shared.u64 t, %1; cvt.u32.u64 %0, t; }"
        : "=r"(a) : "l"(p));
    return a;
}
__device__ __forceinline__ uint32_t swz(uint32_t off) {
    return off ^ ((off >> 3) & 0x70);   // SW128 on 128B rows
}
__device__ __forceinline__ void cp16(uint32_t dst, const void* src) {
    asm volatile("cp.async.cg.shared.global [%0], [%1], 16;"
                 :: "r"(dst), "l"(src));
}
#define CP_COMMIT() asm volatile("cp.async.commit_group;" ::: "memory")
#define CP_WAIT1()  asm volatile("cp.async.wait_group 1;" ::: "memory")
#define CP_WAIT0()  asm volatile("cp.async.wait_group 0;" ::: "memory")

__device__ __forceinline__ void ldm4(uint32_t& r0, uint32_t& r1,
                                     uint32_t& r2, uint32_t& r3, uint32_t a) {
    asm volatile("ldmatrix.sync.aligned.m8n8.x4.shared.b16 {%0,%1,%2,%3}, [%4];"
                 : "=r"(r0), "=r"(r1), "=r"(r2), "=r"(r3) : "r"(a));
}
__device__ __forceinline__ void mma16816(float* c, const uint32_t* a,
                                         const uint32_t* b) {
    asm volatile(
        "mma.sync.aligned.m16n8k16.row.col.f32.f16.f16.f32 "
        "{%0,%1,%2,%3}, {%4,%5,%6,%7}, {%8,%9}, {%0,%1,%2,%3};"
        : "+f"(c[0]), "+f"(c[1]), "+f"(c[2]), "+f"(c[3])
        : "r"(a[0]), "r"(a[1]), "r"(a[2]), "r"(a[3]), "r"(b[0]), "r"(b[1]));
}
__device__ __forceinline__ float tanh_fast(float x) {
    float y;
    asm("tanh.approx.f32 %0, %1;" : "=f"(y) : "f"(x));
    return y;
}

// ================================================================ PREP
#define PB_K1    0
#define PB_TRANS 128
#define PB_SPLIT 1152
#define PREP_BLOCKS (1152 + 32768)

__global__ void k0_zero(float* out) {
    int i = blockIdx.x * blockDim.x + threadIdx.x;   // 0..65535
    g_score[i] = 0.0f;
    if (i < BATCH * HDIM) {
        out[i] = 0.0f;
        g_decproj[i] = 0.0f;
    }
}

__global__ void prep(const float* __restrict__ enc,
                     const float* __restrict__ dec,
                     const float* __restrict__ Wa,
                     const float* __restrict__ Ua) {
    const int bid = blockIdx.x;
    const int tid = threadIdx.x;

    if (bid < PB_TRANS) {
        // ---- k1: dec_proj = dec_hidden @ Wa  (128 blocks)
        __shared__ float dec_s[BATCH][64];
        const int u0 = (bid & 7) * 128;
        const int h0 = (bid >> 3) * 64;
        for (int i = tid; i < BATCH * 64; i += 256) {
            int b = i >> 6, h = i & 63;
            dec_s[b][h] = dec[b * HDIM + h0 + h];
        }
        __syncthreads();
        const int u = u0 + (tid & 127);
        const int hh = (tid >> 7) * 32;
        float acc[BATCH];
        #pragma unroll
        for (int b = 0; b < BATCH; b++) acc[b] = 0.0f;
        #pragma unroll 4
        for (int h = 0; h < 32; h++) {
            float wa = Wa[(size_t)(h0 + hh + h) * UDIM + u];
            #pragma unroll
            for (int b = 0; b < BATCH; b++)
                acc[b] = fmaf(dec_s[b][hh + h], wa, acc[b]);
        }
        #pragma unroll
        for (int b = 0; b < BATCH; b++)
            atomicAdd(&g_decproj[b * UDIM + u], acc[b]);
    } else if (bid < PB_SPLIT) {
        // ---- Ua [H,U] -> transposed [U,H] fp16  (1024 blocks)
        __shared__ float tile[32][33];
        const int rb = bid - PB_TRANS;
        const int u0 = (rb & 31) * 32, h0 = (rb >> 5) * 32;
        const int tx = tid & 31, ty = tid >> 5;   // (32, 8)
        #pragma unroll
        for (int j = 0; j < 4; j++)
            tile[ty + 8 * j][tx] = Ua[(size_t)(h0 + ty + 8 * j) * UDIM + u0 + tx];
        __syncthreads();
        #pragma unroll
        for (int j = 0; j < 4; j++)
            g_ua_t[(size_t)(u0 + ty + 8 * j) * HDIM + h0 + tx] =
                __float2half(tile[tx][ty + 8 * j]);
    } else {
        // ---- enc -> fp16 (32768 blocks, 2 float4 per thread)
        const size_t base = (size_t)(bid - PB_SPLIT) * 512 + tid;
        #pragma unroll
        for (int rep = 0; rep < 2; rep++) {
            size_t i = base + rep * 256;
            float4 v = ((const float4*)enc)[i];
            ushort4 h;
            h.x = __half_as_ushort(__float2half(v.x));
            h.y = __half_as_ushort(__float2half(v.y));
            h.z = __half_as_ushort(__float2half(v.z));
            h.w = __half_as_ushort(__float2half(v.w));
            ((ushort4*)g_enc_h)[i] = h;
        }
    }
}

// ------------------- K2: fused score via fp16 HMMA GEMM + epilogue
// grid (2 u-halves, 512 m-blocks) x 512 threads. CTA tile M=128 x N=256,
// K-chunk 64, 3-stage cp.async, 16 warps (4m x 4n), warp tile m32 x n64.
#define K2_M   128
#define K2_N   256
#define K2_KC  64
#define NT_CNT 2                 // N-slabs per CTA (u-half = 512)
#define KT_CNT (HDIM / K2_KC)    // 16
#define IT_TOT (NT_CNT * KT_CNT) // 32
#define N_STG  3

#define TILE_A   (K2_M * 128)    // 16 KB
#define TILE_Bt  (K2_N * 128)    // 32 KB
#define OFF_A    0
#define OFF_B    (TILE_A)
#define STAGE_B  (TILE_A + TILE_Bt)      // 48 KB
#define SM_BIAS  (N_STG * STAGE_B)       // 147456
#define SM_VA    (SM_BIAS + K2_N * 4)
#define SM_SCORE (SM_VA + K2_N * 4)
#define SM_TOTAL (SM_SCORE + K2_M * 4)   // ~150 KB, 1 CTA/SM

__device__ __forceinline__ void issue_chunk(uint32_t sb, int stage, int row0,
                                            int ubase, int it, int tid) {
    const int nt = it >> 4, kt = it & 15;
    const int u0 = ubase + nt * K2_N;
    const int kg = kt * K2_KC;
    const uint32_t base = sb + stage * STAGE_B;
    // A: 1024 16B segments (128 rows x 8)
    #pragma unroll
    for (int i = 0; i < 2; i++) {
        int s = tid + i * 512;
        int r = s >> 3, seg = s & 7;
        cp16(base + OFF_A + swz((uint32_t)(r * 128 + seg * 16)),
             g_enc_h + (size_t)(row0 + r) * HDIM + kg + seg * 8);
    }
    // B: 2048 16B segments (256 rows x 8)
    #pragma unroll
    for (int i = 0; i < 4; i++) {
        int s = tid + i * 512;
        int r = s >> 3, seg = s & 7;
        cp16(base + OFF_B + swz((uint32_t)(r * 128 + seg * 16)),
             g_ua_t + (size_t)(u0 + r) * HDIM + kg + seg * 8);
    }
}

__global__ void __launch_bounds__(512, 1)
k2_score(const float* __restrict__ Va) {
    extern __shared__ char smem[];
    const uint32_t sb = smem_u32(smem);
    const int tid = threadIdx.x;
    const int lane = tid & 31;
    const int wid = tid >> 5;             // 0..15
    const int warp_m = wid >> 2;          // 0..3 -> m offset *32
    const int warp_n = wid & 3;           // 0..3 -> n offset *64
    const int row0 = blockIdx.y * K2_M;
    const int ubase = blockIdx.x * (NT_CNT * K2_N);   // 0 or 512
    const int b = row0 / TSEQ;

    float* bias_s  = (float*)(smem + SM_BIAS);
    float* va_s    = (float*)(smem + SM_VA);
    float* score_s = (float*)(smem + SM_SCORE);
    if (tid < K2_M) score_s[tid] = 0.0f;

    // prologue: chunks 0,1 -> stages 0,1
    issue_chunk(sb, 0, row0, ubase, 0, tid);
    CP_COMMIT();
    issue_chunk(sb, 1, row0, ubase, 1, tid);
    CP_COMMIT();

    float c[2][8][4];

    for (int it = 0; it < IT_TOT; it++) {
        const int nt = it >> 4, kt = it & 15;
        const int stage = it % N_STG;

        // wait for chunk `it`; single barrier per chunk.
        if (it + 1 < IT_TOT) { CP_WAIT1(); } else { CP_WAIT0(); }
        __syncthreads();

        // issue chunk it+2 into stage (it-1)%3, fully consumed pre-barrier
        if (it + 2 < IT_TOT) {
            issue_chunk(sb, (it + 2) % N_STG, row0, ubase, it + 2, tid);
            CP_COMMIT();
        }

        if (kt == 0) {
            if (tid < K2_N) {
                bias_s[tid] = g_decproj[b * UDIM + ubase + nt * K2_N + tid];
                va_s[tid]   = Va[ubase + nt * K2_N + tid];
            }
            #pragma unroll
            for (int mi = 0; mi < 2; mi++)
                #pragma unroll
                for (int ni = 0; ni < 8; ni++)
                    #pragma unroll
                    for (int q = 0; q < 4; q++)
                        c[mi][ni][q] = 0.0f;
        }

        // ---- compute this chunk (4 x k16 steps)
        const uint32_t aT = sb + stage * STAGE_B + OFF_A;
        const uint32_t bT = sb + stage * STAGE_B + OFF_B;

        #pragma unroll
        for (int ks = 0; ks < 4; ks++) {
            const int kb = ks * 32;  // byte offset of k16 step
            uint32_t ar[2][4];
            #pragma unroll
            for (int mi = 0; mi < 2; mi++) {
                uint32_t rr = warp_m * 32 + mi * 16 + (lane & 15);
                uint32_t off = swz(rr * 128 + kb + (lane >> 4) * 16);
                ldm4(ar[mi][0], ar[mi][1], ar[mi][2], ar[mi][3], aT + off);
            }
            uint32_t br[8][2];
            #pragma unroll
            for (int np = 0; np < 4; np++) {   // each covers 2 n8 tiles
                uint32_t nr = warp_n * 64 + np * 16 + (lane & 7) +
                              ((lane >> 4) ? 8u : 0u);
                uint32_t off = swz(nr * 128 + kb + ((lane >> 3) & 1) * 16);
                uint32_t r0, r1, r2, r3;
                ldm4(r0, r1, r2, r3, bT + off);
                br[np * 2][0] = r0;     br[np * 2][1] = r1;
                br[np * 2 + 1][0] = r2; br[np * 2 + 1][1] = r3;
            }
            #pragma unroll
            for (int mi = 0; mi < 2; mi++)
                #pragma unroll
                for (int ni = 0; ni < 8; ni++)
                    mma16816(c[mi][ni], ar[mi], br[ni]);
        }

        // ---- epilogue at end of each N-slab
        if (kt == KT_CNT - 1) {
            const int qc = lane & 3;
            const int gl = lane >> 2;
            #pragma unroll
            for (int mi = 0; mi < 2; mi++) {
                float s0 = 0.0f, s1 = 0.0f;  // rows r and r+8
                #pragma unroll
                for (int ni = 0; ni < 8; ni++) {
                    int col = warp_n * 64 + ni * 8 + qc * 2;
                    float b0 = bias_s[col], b1 = bias_s[col + 1];
                    float v0 = va_s[col],  v1 = va_s[col + 1];
                    s0 = fmaf(v0, tanh_fast(c[mi][ni][0] + b0), s0);
                    s0 = fmaf(v1, tanh_fast(c[mi][ni][1] + b1), s0);
                    s1 = fmaf(v0, tanh_fast(c[mi][ni][2] + b0), s1);
                    s1 = fmaf(v1, tanh_fast(c[mi][ni][3] + b1), s1);
                }
                s0 += __shfl_xor_sync(0xFFFFFFFF, s0, 1);
                s0 += __shfl_xor_sync(0xFFFFFFFF, s0, 2);
                s1 += __shfl_xor_sync(0xFFFFFFFF, s1, 1);
                s1 += __shfl_xor_sync(0xFFFFFFFF, s1, 2);
                if (qc == 0) {
                    int r = warp_m * 32 + mi * 16 + gl;
                    atomicAdd(&score_s[r], s0);
                    atomicAdd(&score_s[r + 8], s1);
                }
            }
        }
    }

    __syncthreads();   // score_s complete across warps
    if (tid < K2_M) atomicAdd(&g_score[row0 + tid], score_s[tid]);
}

// ---------------------------------------------- K3: softmax over T (in place)
__global__ void k3_softmax() {
    __shared__ float red[1024];
    const int b = blockIdx.x;
    const int tid = threadIdx.x;
    float* row = g_score + (size_t)b * TSEQ;

    float m = fmaxf(row[tid], row[tid + 1024]);
    red[tid] = m; __syncthreads();
    for (int s = 512; s > 0; s >>= 1) {
        if (tid < s) red[tid] = fmaxf(red[tid], red[tid + s]);
        __syncthreads();
    }
    m = red[0];
    __syncthreads();

    float e0 = __expf(row[tid] - m);
    float e1 = __expf(row[tid + 1024] - m);
    red[tid] = e0 + e1; __syncthreads();
    for (int s = 512; s > 0; s >>= 1) {
        if (tid < s) red[tid] += red[tid + s];
        __syncthreads();
    }
    float inv = 1.0f / red[0];
    row[tid] = e0 * inv;
    row[tid + 1024] = e1 * inv;
}

// ------------------------- K4: context[b,h] = sum_t alpha[b,t]*enc_h[b,t,h]
__global__ void k4_context(float* __restrict__ out) {
    __shared__ float al[256];
    const int b = blockIdx.y;
    const int t0 = blockIdx.x * 256;
    const int tid = threadIdx.x;
    al[tid] = g_score[(size_t)b * TSEQ + t0 + tid];
    __syncthreads();

    float4 acc = make_float4(0.f, 0.f, 0.f, 0.f);
    const __half* base = g_enc_h + ((size_t)b * TSEQ + t0) * HDIM + tid * 4;
    #pragma unroll 4
    for (int tt = 0; tt < 256; tt++) {
        float a = al[tt];
        uint2 e = *(const uint2*)(base + (size_t)tt * HDIM);
        float2 f01 = __half22float2(*reinterpret_cast<const __half2*>(&e.x));
        float2 f23 = __half22float2(*reinterpret_cast<const __half2*>(&e.y));
        acc.x = fmaf(a, f01.x, acc.x);
        acc.y = fmaf(a, f01.y, acc.y);
        acc.z = fmaf(a, f23.x, acc.z);
        acc.w = fmaf(a, f23.y, acc.w);
    }
    float* o = out + (size_t)b * HDIM + tid * 4;
    atomicAdd(o + 0, acc.x);
    atomicAdd(o + 1, acc.y);
    atomicAdd(o + 2, acc.z);
    atomicAdd(o + 3, acc.w);
}

// ------------------------------------------------------------------- launcher
extern "C" void kernel_launch(void* const* d_in, const int* in_sizes, int n_in,
                              void* d_out, int out_size) {
    const float* enc = (const float*)d_in[0];
    const float* dec = (const float*)d_in[1];
    const float* Wa  = (const float*)d_in[2];
    const float* Ua  = (const float*)d_in[3];
    const float* Va  = (const float*)d_in[4];
    float* out = (float*)d_out;
    (void)in_sizes; (void)n_in; (void)out_size;

    cudaFuncSetAttribute(k2_score, cudaFuncAttributeMaxDynamicSharedMemorySize,
                         SM_TOTAL);

    k0_zero<<<BT / 256, 256>>>(out);          // zero atomic targets first
    prep<<<PREP_BLOCKS, 256>>>(enc, dec, Wa, Ua);
    k2_score<<<dim3(2, BT / K2_M), 512, SM_TOTAL>>>(Va);
    k3_softmax<<<BATCH, 1024>>>();
    k4_context<<<dim3(TSEQ / 256, BATCH), 256>>>(out);
}

// round 13
// speedup vs baseline: 1.0814x; 1.0814x over previous
#include <cuda_runtime.h>
#include <cuda_fp16.h>
#include <cstdint>
#include <math.h>

// Bahdanau additive attention, sm_103 base target (no tcgen05).
// R13: revert to R11 k2 shape (M128xN128, 256thr, occ2 — best known) and
// split U 4-way -> 2048 CTAs, 6.92 waves (1% tail vs 13%). Traffic identical.

#define BATCH 32
#define TSEQ  2048
#define HDIM  1024
#define UDIM  1024
#define BT    (BATCH * TSEQ)

// ---------------------------------------------------------------- scratch
__device__ float g_score[BT];
__device__ float g_decproj[BATCH * UDIM];
__device__ __half g_enc_h[(size_t)BT * HDIM];     // 128 MB
__device__ __half g_ua_t[(size_t)UDIM * HDIM];    // transposed [U][H]

// ---------------------------------------------------------------- helpers
__device__ __forceinline__ uint32_t smem_u32(const void* p) {
    uint32_t a;
    asm("{ .reg .u64 t; cvta.to.shared.u64 t, %1; cvt.u32.u64 %0, t; }"
        : "=r"(a) : "l"(p));
    return a;
}
__device__ __forceinline__ uint32_t swz(uint32_t off) {
    return off ^ ((off >> 3) & 0x70);   // SW128 on 128B rows
}
__device__ __forceinline__ void cp16(uint32_t dst, const void* src) {
    asm volatile("cp.async.cg.shared.global [%0], [%1], 16;"
                 :: "r"(dst), "l"(src));
}
#define CP_COMMIT() asm volatile("cp.async.commit_group;" ::: "memory")
#define CP_WAIT1()  asm volatile("cp.async.wait_group 1;" ::: "memory")
#define CP_WAIT0()  asm volatile("cp.async.wait_group 0;" ::: "memory")

__device__ __forceinline__ void ldm4(uint32_t& r0, uint32_t& r1,
                                     uint32_t& r2, uint32_t& r3, uint32_t a) {
    asm volatile("ldmatrix.sync.aligned.m8n8.x4.shared.b16 {%0,%1,%2,%3}, [%4];"
                 : "=r"(r0), "=r"(r1), "=r"(r2), "=r"(r3) : "r"(a));
}
__device__ __forceinline__ void mma16816(float* c, const uint32_t* a,
                                         const uint32_t* b) {
    asm volatile(
        "mma.sync.aligned.m16n8k16.row.col.f32.f16.f16.f32 "
        "{%0,%1,%2,%3}, {%4,%5,%6,%7}, {%8,%9}, {%0,%1,%2,%3};"
        : "+f"(c[0]), "+f"(c[1]), "+f"(c[2]), "+f"(c[3])
        : "r"(a[0]), "r"(a[1]), "r"(a[2]), "r"(a[3]), "r"(b[0]), "r"(b[1]));
}
__device__ __forceinline__ float tanh_fast(float x) {
    float y;
    asm("tanh.approx.f32 %0, %1;" : "=f"(y) : "f"(x));
    return y;
}

// ================================================================ PREP
#define PB_K1    0
#define PB_TRANS 128
#define PB_SPLIT 1152
#define PREP_BLOCKS (1152 + 32768)

__global__ void k0_zero(float* out) {
    int i = blockIdx.x * blockDim.x + threadIdx.x;   // 0..65535
    g_score[i] = 0.0f;
    if (i < BATCH * HDIM) {
        out[i] = 0.0f;
        g_decproj[i] = 0.0f;
    }
}

__global__ void prep(const float* __restrict__ enc,
                     const float* __restrict__ dec,
                     const float* __restrict__ Wa,
                     const float* __restrict__ Ua) {
    const int bid = blockIdx.x;
    const int tid = threadIdx.x;

    if (bid < PB_TRANS) {
        // ---- k1: dec_proj = dec_hidden @ Wa  (128 blocks)
        __shared__ float dec_s[BATCH][64];
        const int u0 = (bid & 7) * 128;
        const int h0 = (bid >> 3) * 64;
        for (int i = tid; i < BATCH * 64; i += 256) {
            int b = i >> 6, h = i & 63;
            dec_s[b][h] = dec[b * HDIM + h0 + h];
        }
        __syncthreads();
        const int u = u0 + (tid & 127);
        const int hh = (tid >> 7) * 32;
        float acc[BATCH];
        #pragma unroll
        for (int b = 0; b < BATCH; b++) acc[b] = 0.0f;
        #pragma unroll 4
        for (int h = 0; h < 32; h++) {
            float wa = Wa[(size_t)(h0 + hh + h) * UDIM + u];
            #pragma unroll
            for (int b = 0; b < BATCH; b++)
                acc[b] = fmaf(dec_s[b][hh + h], wa, acc[b]);
        }
        #pragma unroll
        for (int b = 0; b < BATCH; b++)
            atomicAdd(&g_decproj[b * UDIM + u], acc[b]);
    } else if (bid < PB_SPLIT) {
        // ---- Ua [H,U] -> transposed [U,H] fp16  (1024 blocks)
        __shared__ float tile[32][33];
        const int rb = bid - PB_TRANS;
        const int u0 = (rb & 31) * 32, h0 = (rb >> 5) * 32;
        const int tx = tid & 31, ty = tid >> 5;   // (32, 8)
        #pragma unroll
        for (int j = 0; j < 4; j++)
            tile[ty + 8 * j][tx] = Ua[(size_t)(h0 + ty + 8 * j) * UDIM + u0 + tx];
        __syncthreads();
        #pragma unroll
        for (int j = 0; j < 4; j++)
            g_ua_t[(size_t)(u0 + ty + 8 * j) * HDIM + h0 + tx] =
                __float2half(tile[tx][ty + 8 * j]);
    } else {
        // ---- enc -> fp16 (32768 blocks, 2 float4 per thread)
        const size_t base = (size_t)(bid - PB_SPLIT) * 512 + tid;
        #pragma unroll
        for (int rep = 0; rep < 2; rep++) {
            size_t i = base + rep * 256;
            float4 v = ((const float4*)enc)[i];
            ushort4 h;
            h.x = __half_as_ushort(__float2half(v.x));
            h.y = __half_as_ushort(__float2half(v.y));
            h.z = __half_as_ushort(__float2half(v.z));
            h.w = __half_as_ushort(__float2half(v.w));
            ((ushort4*)g_enc_h)[i] = h;
        }
    }
}

// ------------------- K2: fused score via fp16 HMMA GEMM + epilogue
// grid (4 u-quarters, 512 m-blocks) x 256 threads, occupancy 2.
// CTA: M=128 rows x u-quarter (2 N-slabs of 128), K-chunk 64, 3-stage
// cp.async, single sync per chunk. Warp grid 4m x 2n, warp tile m32 x n64.
#define K2_M   128
#define K2_N   128
#define K2_KC  64
#define NT_CNT 2                 // N-slabs per CTA (u-quarter = 256)
#define KT_CNT (HDIM / K2_KC)    // 16
#define IT_TOT (NT_CNT * KT_CNT) // 32
#define N_STG  3

#define TILE_B   (128 * 128)     // [128 rows][64 fp16] = 16 KB
#define OFF_A    0
#define OFF_B    (TILE_B)
#define STAGE_B  (2 * TILE_B)    // 32 KB
#define SM_BIAS  (N_STG * STAGE_B)
#define SM_VA    (SM_BIAS + K2_N * 4)
#define SM_SCORE (SM_VA + K2_N * 4)
#define SM_TOTAL (SM_SCORE + K2_M * 4)   // ~99.8 KB ; 2 CTAs <= 228

__device__ __forceinline__ void issue_chunk(uint32_t sb, int stage, int row0,
                                            int ubase, int it, int tid) {
    const int nt = it >> 4, kt = it & 15;
    const int u0 = ubase + nt * K2_N;
    const int kg = kt * K2_KC;
    const uint32_t base = sb + stage * STAGE_B;
    #pragma unroll
    for (int i = 0; i < 4; i++) {
        int s = tid + i * 256;        // 0..1023
        int r = s >> 3, seg = s & 7;  // row, 16B segment
        uint32_t so = swz((uint32_t)(r * 128 + seg * 16));
        cp16(base + OFF_A + so, g_enc_h + (size_t)(row0 + r) * HDIM + kg + seg * 8);
        cp16(base + OFF_B + so, g_ua_t + (size_t)(u0 + r) * HDIM + kg + seg * 8);
    }
}

__global__ void __launch_bounds__(256, 2)
k2_score(const float* __restrict__ Va) {
    extern __shared__ char smem[];
    const uint32_t sb = smem_u32(smem);
    const int tid = threadIdx.x;
    const int lane = tid & 31;
    const int wid = tid >> 5;
    const int warp_m = wid >> 1;          // 0..3 -> m offset *32
    const int warp_n = wid & 1;           // 0..1 -> n offset *64
    const int row0 = blockIdx.y * K2_M;
    const int ubase = blockIdx.x * (NT_CNT * K2_N);   // 0,256,512,768
    const int b = row0 / TSEQ;

    float* bias_s  = (float*)(smem + SM_BIAS);
    float* va_s    = (float*)(smem + SM_VA);
    float* score_s = (float*)(smem + SM_SCORE);
    if (tid < K2_M) score_s[tid] = 0.0f;

    // prologue: chunks 0,1 -> stages 0,1
    issue_chunk(sb, 0, row0, ubase, 0, tid);
    CP_COMMIT();
    issue_chunk(sb, 1, row0, ubase, 1, tid);
    CP_COMMIT();

    float c[2][8][4];

    for (int it = 0; it < IT_TOT; it++) {
        const int nt = it >> 4, kt = it & 15;
        const int stage = it % N_STG;

        // wait for chunk `it`; single barrier per chunk.
        if (it + 1 < IT_TOT) { CP_WAIT1(); } else { CP_WAIT0(); }
        __syncthreads();

        // issue chunk it+2 into stage (it-1)%3, fully consumed pre-barrier
        if (it + 2 < IT_TOT) {
            issue_chunk(sb, (it + 2) % N_STG, row0, ubase, it + 2, tid);
            CP_COMMIT();
        }

        if (kt == 0) {
            if (tid < K2_N) {
                bias_s[tid] = g_decproj[b * UDIM + ubase + nt * K2_N + tid];
                va_s[tid]   = Va[ubase + nt * K2_N + tid];
            }
            #pragma unroll
            for (int mi = 0; mi < 2; mi++)
                #pragma unroll
                for (int ni = 0; ni < 8; ni++)
                    #pragma unroll
                    for (int q = 0; q < 4; q++)
                        c[mi][ni][q] = 0.0f;
        }

        // ---- compute this chunk (4 x k16 steps)
        const uint32_t aT = sb + stage * STAGE_B + OFF_A;
        const uint32_t bT = sb + stage * STAGE_B + OFF_B;

        #pragma unroll
        for (int ks = 0; ks < 4; ks++) {
            const int kb = ks * 32;  // byte offset of k16 step
            uint32_t ar[2][4];
            #pragma unroll
            for (int mi = 0; mi < 2; mi++) {
                uint32_t rr = warp_m * 32 + mi * 16 + (lane & 15);
                uint32_t off = swz(rr * 128 + kb + (lane >> 4) * 16);
                ldm4(ar[mi][0], ar[mi][1], ar[mi][2], ar[mi][3], aT + off);
            }
            uint32_t br[8][2];
            #pragma unroll
            for (int np = 0; np < 4; np++) {   // each covers 2 n8 tiles
                uint32_t nr = warp_n * 64 + np * 16 + (lane & 7) +
                              ((lane >> 4) ? 8u : 0u);
                uint32_t off = swz(nr * 128 + kb + ((lane >> 3) & 1) * 16);
                uint32_t r0, r1, r2, r3;
                ldm4(r0, r1, r2, r3, bT + off);
                br[np * 2][0] = r0;     br[np * 2][1] = r1;
                br[np * 2 + 1][0] = r2; br[np * 2 + 1][1] = r3;
            }
            #pragma unroll
            for (int mi = 0; mi < 2; mi++)
                #pragma unroll
                for (int ni = 0; ni < 8; ni++)
                    mma16816(c[mi][ni], ar[mi], br[ni]);
        }

        // ---- epilogue at end of each N-slab
        if (kt == KT_CNT - 1) {
            const int qc = lane & 3;
            const int gl = lane >> 2;
            #pragma unroll
            for (int mi = 0; mi < 2; mi++) {
                float s0 = 0.0f, s1 = 0.0f;  // rows r and r+8
                #pragma unroll
                for (int ni = 0; ni < 8; ni++) {
                    int col = warp_n * 64 + ni * 8 + qc * 2;
                    float b0 = bias_s[col], b1 = bias_s[col + 1];
                    float v0 = va_s[col],  v1 = va_s[col + 1];
                    s0 = fmaf(v0, tanh_fast(c[mi][ni][0] + b0), s0);
                    s0 = fmaf(v1, tanh_fast(c[mi][ni][1] + b1), s0);
                    s1 = fmaf(v0, tanh_fast(c[mi][ni][2] + b0), s1);
                    s1 = fmaf(v1, tanh_fast(c[mi][ni][3] + b1), s1);
                }
                s0 += __shfl_xor_sync(0xFFFFFFFF, s0, 1);
                s0 += __shfl_xor_sync(0xFFFFFFFF, s0, 2);
                s1 += __shfl_xor_sync(0xFFFFFFFF, s1, 1);
                s1 += __shfl_xor_sync(0xFFFFFFFF, s1, 2);
                if (qc == 0) {
                    int r = warp_m * 32 + mi * 16 + gl;
                    atomicAdd(&score_s[r], s0);
                    atomicAdd(&score_s[r + 8], s1);
                }
            }
        }
    }

    __syncthreads();   // score_s complete across warps
    if (tid < K2_M) atomicAdd(&g_score[row0 + tid], score_s[tid]);
}

// ---------------------------------------------- K3: softmax over T (in place)
__global__ void k3_softmax() {
    __shared__ float red[1024];
    const int b = blockIdx.x;
    const int tid = threadIdx.x;
    float* row = g_score + (size_t)b * TSEQ;

    float m = fmaxf(row[tid], row[tid + 1024]);
    red[tid] = m; __syncthreads();
    for (int s = 512; s > 0; s >>= 1) {
        if (tid < s) red[tid] = fmaxf(red[tid], red[tid + s]);
        __syncthreads();
    }
    m = red[0];
    __syncthreads();

    float e0 = __expf(row[tid] - m);
    float e1 = __expf(row[tid + 1024] - m);
    red[tid] = e0 + e1; __syncthreads();
    for (int s = 512; s > 0; s >>= 1) {
        if (tid < s) red[tid] += red[tid + s];
        __syncthreads();
    }
    float inv = 1.0f / red[0];
    row[tid] = e0 * inv;
    row[tid + 1024] = e1 * inv;
}

// ------------------------- K4: context[b,h] = sum_t alpha[b,t]*enc_h[b,t,h]
__global__ void k4_context(float* __restrict__ out) {
    __shared__ float al[256];
    const int b = blockIdx.y;
    const int t0 = blockIdx.x * 256;
    const int tid = threadIdx.x;
    al[tid] = g_score[(size_t)b * TSEQ + t0 + tid];
    __syncthreads();

    float4 acc = make_float4(0.f, 0.f, 0.f, 0.f);
    const __half* base = g_enc_h + ((size_t)b * TSEQ + t0) * HDIM + tid * 4;
    #pragma unroll 4
    for (int tt = 0; tt < 256; tt++) {
        float a = al[tt];
        uint2 e = *(const uint2*)(base + (size_t)tt * HDIM);
        float2 f01 = __half22float2(*reinterpret_cast<const __half2*>(&e.x));
        float2 f23 = __half22float2(*reinterpret_cast<const __half2*>(&e.y));
        acc.x = fmaf(a, f01.x, acc.x);
        acc.y = fmaf(a, f01.y, acc.y);
        acc.z = fmaf(a, f23.x, acc.z);
        acc.w = fmaf(a, f23.y, acc.w);
    }
    float* o = out + (size_t)b * HDIM + tid * 4;
    atomicAdd(o + 0, acc.x);
    atomicAdd(o + 1, acc.y);
    atomicAdd(o + 2, acc.z);
    atomicAdd(o + 3, acc.w);
}

// ------------------------------------------------------------------- launcher
extern "C" void kernel_launch(void* const* d_in, const int* in_sizes, int n_in,
                              void* d_out, int out_size) {
    const float* enc = (const float*)d_in[0];
    const float* dec = (const float*)d_in[1];
    const float* Wa  = (const float*)d_in[2];
    const float* Ua  = (const float*)d_in[3];
    const float* Va  = (const float*)d_in[4];
    float* out = (float*)d_out;
    (void)in_sizes; (void)n_in; (void)out_size;

    cudaFuncSetAttribute(k2_score, cudaFuncAttributeMaxDynamicSharedMemorySize,
                         SM_TOTAL);

    k0_zero<<<BT / 256, 256>>>(out);          // zero atomic targets first
    prep<<<PREP_BLOCKS, 256>>>(enc, dec, Wa, Ua);
    k2_score<<<dim3(4, BT / K2_M), 256, SM_TOTAL>>>(Va);
    k3_softmax<<<BATCH, 1024>>>();
    k4_context<<<dim3(TSEQ / 256, BATCH), 256>>>(out);
}